// round 5
// baseline (speedup 1.0000x reference)
#include <cuda_runtime.h>
#include <math.h>
#include <stdint.h>

// Problem constants
#define Bn 4
#define Tn 2048
#define Dn 1024
#define Hn 16
#define HS 64
#define Mrows (Bn*Tn)          // 8192

// Scratch (device globals; no runtime allocation allowed)
__device__ float g_q[(size_t)Bn*Hn*Tn*HS];   // [B,H,T,hs] rope'd, scaled, tf32-rounded
__device__ float g_k[(size_t)Bn*Hn*Tn*HS];   // [B,H,T,hs] rope'd, tf32-rounded
__device__ float g_v[(size_t)Bn*Hn*Tn*HS];   // [B,H,T,hs] tf32-rounded
__device__ float g_ao[(size_t)Bn*Tn*Dn];     // attention output [B*T, D]
__device__ float2 g_rope[Tn*32];             // (cos, sin) table

// ---------------------------------------------------------------------------
// helpers
// ---------------------------------------------------------------------------
__device__ __forceinline__ uint32_t f2tf(float x) {
    uint32_t u;
    asm("cvt.rna.tf32.f32 %0, %1;" : "=r"(u) : "f"(x));
    return u;
}

__device__ __forceinline__ float ex2(float x) {
    float y;
    asm("ex2.approx.f32 %0, %1;" : "=f"(y) : "f"(x));
    return y;
}

__device__ __forceinline__ void mma_tf32(float c[4],
                                         uint32_t a0, uint32_t a1, uint32_t a2, uint32_t a3,
                                         uint32_t b0, uint32_t b1)
{
    asm volatile(
        "mma.sync.aligned.m16n8k8.row.col.f32.tf32.tf32.f32 "
        "{%0,%1,%2,%3}, {%4,%5,%6,%7}, {%8,%9}, {%0,%1,%2,%3};\n"
        : "+f"(c[0]), "+f"(c[1]), "+f"(c[2]), "+f"(c[3])
        : "r"(a0), "r"(a1), "r"(a2), "r"(a3), "r"(b0), "r"(b1));
}

__device__ __forceinline__ int sw_idx(int row, int k) {
    return row * 16 + (k ^ (((row >> 1) & 3) << 2));
}

// ---------------------------------------------------------------------------
// RoPE table init
// ---------------------------------------------------------------------------
__global__ void rope_init()
{
    int idx = blockIdx.x * blockDim.x + threadIdx.x;  // 0..65535
    int t = idx >> 5;
    int i = idx & 31;
    float theta = powf(10000.0f, (float)i * (-2.0f / 64.0f));
    float ang = (float)t * theta;
    float sn, cs;
    sincosf(ang, &sn, &cs);
    g_rope[idx] = make_float2(cs, sn);
}

// ---------------------------------------------------------------------------
// tf32 tensor-core GEMM: C[M,N] = A[M,1024] @ W[N,1024]^T (row-major)
// Block 128x128, BK=16, 256 threads = 8 warps (2x4), warp tile 64x32.
// Double-buffered smem, ONE __syncthreads per k-tile.
// MODE 0: QKV epilogue (table-RoPE scatter; outputs tf32-rounded)
// MODE 1: proj epilogue (bias add -> out), A taken from g_ao
// ---------------------------------------------------------------------------
template<int MODE>
__global__ void __launch_bounds__(256) gemm_tf32(const float* __restrict__ A,
                                                 const float* __restrict__ W,
                                                 const float* __restrict__ bias,
                                                 float* __restrict__ out)
{
    __shared__ __align__(16) uint32_t As[2][128 * 16];
    __shared__ __align__(16) uint32_t Ws[2][128 * 16];

    const int m0 = blockIdx.y * 128;
    const int n0 = blockIdx.x * 128;
    const int tid = threadIdx.x;
    const int wid = tid >> 5;
    const int lane = tid & 31;
    const int wm = wid >> 2;
    const int wn = wid & 3;
    const int gq = lane >> 2;
    const int tq = lane & 3;

    const int lrow = tid >> 2;
    const int lkc = (tid & 3) << 2;
    const int sw0 = sw_idx(lrow, lkc);
    const int sw1 = sw0 + 64 * 16;

    const float* Abase = (MODE == 1) ? (const float*)g_ao : A;
    const float* Ap0 = Abase + (size_t)(m0 + lrow) * 1024 + lkc;
    const float* Ap1 = Ap0 + (size_t)64 * 1024;
    const float* Wp0 = W + (size_t)(n0 + lrow) * 1024 + lkc;
    const float* Wp1 = Wp0 + (size_t)64 * 1024;

    float acc[4][4][4];
    #pragma unroll
    for (int mt = 0; mt < 4; mt++)
        #pragma unroll
        for (int nt = 0; nt < 4; nt++)
            #pragma unroll
            for (int r = 0; r < 4; r++) acc[mt][nt][r] = 0.f;

    // prologue: stage 0
    {
        float4 a0v = *(const float4*)(Ap0);
        float4 a1v = *(const float4*)(Ap1);
        float4 w0v = *(const float4*)(Wp0);
        float4 w1v = *(const float4*)(Wp1);
        uint4 u;
        u.x = f2tf(a0v.x); u.y = f2tf(a0v.y); u.z = f2tf(a0v.z); u.w = f2tf(a0v.w);
        *(uint4*)&As[0][sw0] = u;
        u.x = f2tf(a1v.x); u.y = f2tf(a1v.y); u.z = f2tf(a1v.z); u.w = f2tf(a1v.w);
        *(uint4*)&As[0][sw1] = u;
        u.x = f2tf(w0v.x); u.y = f2tf(w0v.y); u.z = f2tf(w0v.z); u.w = f2tf(w0v.w);
        *(uint4*)&Ws[0][sw0] = u;
        u.x = f2tf(w1v.x); u.y = f2tf(w1v.y); u.z = f2tf(w1v.z); u.w = f2tf(w1v.w);
        *(uint4*)&Ws[0][sw1] = u;
    }
    __syncthreads();

    int st = 0;
    for (int k0 = 0; k0 < 1024; k0 += 16) {
        const bool more = (k0 + 16 < 1024);
        float4 a0v, a1v, w0v, w1v;
        if (more) {
            a0v = *(const float4*)(Ap0 + k0 + 16);
            a1v = *(const float4*)(Ap1 + k0 + 16);
            w0v = *(const float4*)(Wp0 + k0 + 16);
            w1v = *(const float4*)(Wp1 + k0 + 16);
        }

        const uint32_t* Acur = As[st];
        const uint32_t* Wcur = Ws[st];
        #pragma unroll
        for (int ks = 0; ks < 2; ks++) {
            uint32_t af[4][4];
            uint32_t bf[4][2];
            #pragma unroll
            for (int mt = 0; mt < 4; mt++) {
                int mb = wm * 64 + mt * 16 + gq;
                int swm = ((mb >> 1) & 3) << 2;
                int klo = ks * 8 + tq;
                af[mt][0] = Acur[mb * 16 + (klo ^ swm)];
                af[mt][1] = Acur[(mb + 8) * 16 + (klo ^ swm)];
                af[mt][2] = Acur[mb * 16 + ((klo + 4) ^ swm)];
                af[mt][3] = Acur[(mb + 8) * 16 + ((klo + 4) ^ swm)];
            }
            #pragma unroll
            for (int nt = 0; nt < 4; nt++) {
                int nb = wn * 32 + nt * 8 + gq;
                int swn = ((nb >> 1) & 3) << 2;
                int klo = ks * 8 + tq;
                bf[nt][0] = Wcur[nb * 16 + (klo ^ swn)];
                bf[nt][1] = Wcur[nb * 16 + ((klo + 4) ^ swn)];
            }
            #pragma unroll
            for (int mt = 0; mt < 4; mt++)
                #pragma unroll
                for (int nt = 0; nt < 4; nt++)
                    mma_tf32(acc[mt][nt], af[mt][0], af[mt][1], af[mt][2], af[mt][3],
                             bf[nt][0], bf[nt][1]);
        }

        if (more) {
            uint32_t* An = As[st ^ 1];
            uint32_t* Wn = Ws[st ^ 1];
            uint4 u;
            u.x = f2tf(a0v.x); u.y = f2tf(a0v.y); u.z = f2tf(a0v.z); u.w = f2tf(a0v.w);
            *(uint4*)&An[sw0] = u;
            u.x = f2tf(a1v.x); u.y = f2tf(a1v.y); u.z = f2tf(a1v.z); u.w = f2tf(a1v.w);
            *(uint4*)&An[sw1] = u;
            u.x = f2tf(w0v.x); u.y = f2tf(w0v.y); u.z = f2tf(w0v.z); u.w = f2tf(w0v.w);
            *(uint4*)&Wn[sw0] = u;
            u.x = f2tf(w1v.x); u.y = f2tf(w1v.y); u.z = f2tf(w1v.z); u.w = f2tf(w1v.w);
            *(uint4*)&Wn[sw1] = u;
        }
        __syncthreads();
        st ^= 1;
    }

    if (MODE == 0) {
        const float QSC = 0.125f * 1.4426950408889634f;  // scale * log2(e)
        #pragma unroll
        for (int mt = 0; mt < 4; mt++) {
            #pragma unroll
            for (int r = 0; r < 2; r++) {
                int m = m0 + wm * 64 + mt * 16 + gq + r * 8;
                int bb = m >> 11;
                int tt = m & 2047;
                #pragma unroll
                for (int nt = 0; nt < 4; nt++) {
                    int col = n0 + wn * 32 + nt * 8 + 2 * tq;
                    int which = col >> 10;
                    int rem = col & 1023;
                    int h = rem >> 6;
                    int d = rem & 63;
                    size_t off = ((size_t)((bb * Hn + h) * Tn + tt)) * HS + d;
                    float e = acc[mt][nt][r * 2 + 0];
                    float o = acc[mt][nt][r * 2 + 1];
                    if (which == 2) {
                        float2 v2;
                        v2.x = __uint_as_float(f2tf(e));
                        v2.y = __uint_as_float(f2tf(o));
                        *(float2*)(g_v + off) = v2;
                    } else {
                        float2 cs = g_rope[tt * 32 + (d >> 1)];
                        float t1 = e * cs.x - o * cs.y;
                        float t2 = e * cs.y + o * cs.x;
                        float2 v2;
                        if (which == 0) {
                            v2.x = __uint_as_float(f2tf(t1));
                            v2.y = __uint_as_float(f2tf(t2));
                            *(float2*)(g_k + off) = v2;
                        } else {
                            v2.x = __uint_as_float(f2tf(t1 * QSC));
                            v2.y = __uint_as_float(f2tf(t2 * QSC));
                            *(float2*)(g_q + off) = v2;
                        }
                    }
                }
            }
        }
    } else {
        #pragma unroll
        for (int mt = 0; mt < 4; mt++) {
            #pragma unroll
            for (int r = 0; r < 2; r++) {
                int m = m0 + wm * 64 + mt * 16 + gq + r * 8;
                #pragma unroll
                for (int nt = 0; nt < 4; nt++) {
                    int col = n0 + wn * 32 + nt * 8 + 2 * tq;
                    float2 v2;
                    v2.x = acc[mt][nt][r * 2 + 0] + bias[col + 0];
                    v2.y = acc[mt][nt][r * 2 + 1] + bias[col + 1];
                    *(float2*)(out + (size_t)m * 1024 + col) = v2;
                }
            }
        }
    }
}

// ---------------------------------------------------------------------------
// Tensor-core causal flash attention (tf32 mma.sync).
// Block: 128 q-rows, 8 warps x m16, 256 threads, 2 CTAs/SM (16 warps/SM).
// K/V/Q already tf32-rounded in global; staging is a bit copy.
// grid = (16, 64); blockIdx.x reversed -> heavy (long-ntile) blocks first.
// ---------------------------------------------------------------------------
#define SMEM_ATTN ((64*68*2 + 128*68) * 4)

__global__ void __launch_bounds__(256, 2) attn_mma()
{
    extern __shared__ __align__(16) char smraw[];
    uint32_t* Ks = (uint32_t*)smraw;        // [64*68] tf32 bits
    uint32_t* Vs = Ks + 64 * 68;            // [64*68] tf32 bits
    float*    Ps = (float*)(Vs + 64 * 68);  // [128*68] (Q staging, then P)

    const int bh = blockIdx.y;
    const int qt = gridDim.x - 1 - blockIdx.x;   // heavy blocks launch first
    const int tid = threadIdx.x;
    const int wid = tid >> 5;
    const int lane = tid & 31;
    const int gq = lane >> 2;
    const int tq = lane & 3;
    const int qb = qt * 128;
    const int wrow = wid * 16;

    const size_t base = (size_t)bh * Tn * HS;
    const float* Qp = g_q + base;
    const float* Kp = g_k + base;
    const float* Vp = g_v + base;

    // stage Q tile into Ps (128 rows x 64 cols; bit copy, already tf32/scaled)
    #pragma unroll
    for (int l = 0; l < 8; l++) {
        int idx = tid + l * 256;
        int rr = idx >> 4;
        int cc = (idx & 15) << 2;
        float4 v = *(const float4*)(Qp + (size_t)(qb + rr) * HS + cc);
        *(float4*)&Ps[rr * 68 + cc] = v;
    }
    __syncthreads();

    const int r0off = (wrow + gq) * 68;
    const int r1off = (wrow + gq + 8) * 68;

    uint32_t qf[8][4];
    #pragma unroll
    for (int kk = 0; kk < 8; kk++) {
        qf[kk][0] = __float_as_uint(Ps[r0off + kk * 8 + tq]);
        qf[kk][1] = __float_as_uint(Ps[r1off + kk * 8 + tq]);
        qf[kk][2] = __float_as_uint(Ps[r0off + kk * 8 + tq + 4]);
        qf[kk][3] = __float_as_uint(Ps[r1off + kk * 8 + tq + 4]);
    }
    __syncwarp();

    float O[8][4];
    #pragma unroll
    for (int nt = 0; nt < 8; nt++)
        #pragma unroll
        for (int r = 0; r < 4; r++) O[nt][r] = 0.f;
    float m0 = -INFINITY, m1 = -INFINITY;
    float l0 = 0.f, l1 = 0.f;

    const int ntiles = 2 * qt + 2;
    for (int kt = 0; kt < ntiles; kt++) {
        const int k0 = kt * 64;
        __syncthreads();
        #pragma unroll
        for (int l = 0; l < 4; l++) {
            int idx = tid + l * 256;
            int rr = idx >> 4;
            int cc = (idx & 15) << 2;
            uint4 ku = *(const uint4*)(Kp + (size_t)(k0 + rr) * HS + cc);
            uint4 vu = *(const uint4*)(Vp + (size_t)(k0 + rr) * HS + cc);
            *(uint4*)&Ks[rr * 68 + cc] = ku;
            *(uint4*)&Vs[rr * 68 + cc] = vu;
        }
        __syncthreads();

        if (k0 > qb + wrow + 15) continue;   // tile fully masked for this warp

        // ---- S = Q K^T ----
        float S[8][4];
        #pragma unroll
        for (int nt = 0; nt < 8; nt++)
            #pragma unroll
            for (int r = 0; r < 4; r++) S[nt][r] = 0.f;

        #pragma unroll
        for (int kk = 0; kk < 8; kk++) {
            #pragma unroll
            for (int nt = 0; nt < 8; nt++) {
                uint32_t b0 = Ks[(nt * 8 + gq) * 68 + kk * 8 + tq];
                uint32_t b1 = Ks[(nt * 8 + gq) * 68 + kk * 8 + tq + 4];
                mma_tf32(S[nt], qf[kk][0], qf[kk][1], qf[kk][2], qf[kk][3], b0, b1);
            }
        }

        // ---- causal mask (diagonal region only) ----
        if (k0 + 63 > qb + wrow) {
            int row0 = qb + wrow + gq;
            #pragma unroll
            for (int nt = 0; nt < 8; nt++) {
                int col = k0 + nt * 8 + 2 * tq;
                if (col     > row0)     S[nt][0] = -INFINITY;
                if (col + 1 > row0)     S[nt][1] = -INFINITY;
                if (col     > row0 + 8) S[nt][2] = -INFINITY;
                if (col + 1 > row0 + 8) S[nt][3] = -INFINITY;
            }
        }

        // ---- online softmax ----
        float cm0 = -INFINITY, cm1 = -INFINITY;
        #pragma unroll
        for (int nt = 0; nt < 8; nt++) {
            cm0 = fmaxf(cm0, fmaxf(S[nt][0], S[nt][1]));
            cm1 = fmaxf(cm1, fmaxf(S[nt][2], S[nt][3]));
        }
        cm0 = fmaxf(cm0, __shfl_xor_sync(0xffffffff, cm0, 1));
        cm0 = fmaxf(cm0, __shfl_xor_sync(0xffffffff, cm0, 2));
        cm1 = fmaxf(cm1, __shfl_xor_sync(0xffffffff, cm1, 1));
        cm1 = fmaxf(cm1, __shfl_xor_sync(0xffffffff, cm1, 2));

        float mn0 = fmaxf(m0, cm0);
        float mn1 = fmaxf(m1, cm1);
        float c0 = ex2(m0 - mn0);
        float c1 = ex2(m1 - mn1);
        l0 *= c0; l1 *= c1;
        #pragma unroll
        for (int nt = 0; nt < 8; nt++) {
            O[nt][0] *= c0; O[nt][1] *= c0;
            O[nt][2] *= c1; O[nt][3] *= c1;
        }
        m0 = mn0; m1 = mn1;

        __syncwarp();   // prior PV reads of Ps complete before overwrite
        #pragma unroll
        for (int nt = 0; nt < 8; nt++) {
            float p0 = ex2(S[nt][0] - mn0);
            float p1 = ex2(S[nt][1] - mn0);
            float p2 = ex2(S[nt][2] - mn1);
            float p3 = ex2(S[nt][3] - mn1);
            l0 += p0 + p1;
            l1 += p2 + p3;
            float2 w0; w0.x = __uint_as_float(f2tf(p0)); w0.y = __uint_as_float(f2tf(p1));
            float2 w1; w1.x = __uint_as_float(f2tf(p2)); w1.y = __uint_as_float(f2tf(p3));
            *(float2*)&Ps[r0off + nt * 8 + 2 * tq] = w0;
            *(float2*)&Ps[r1off + nt * 8 + 2 * tq] = w1;
        }
        __syncwarp();   // P visible to whole warp

        // ---- O += P V ----
        #pragma unroll
        for (int kk = 0; kk < 8; kk++) {
            uint32_t a0 = __float_as_uint(Ps[r0off + kk * 8 + tq]);
            uint32_t a1 = __float_as_uint(Ps[r1off + kk * 8 + tq]);
            uint32_t a2 = __float_as_uint(Ps[r0off + kk * 8 + tq + 4]);
            uint32_t a3 = __float_as_uint(Ps[r1off + kk * 8 + tq + 4]);
            #pragma unroll
            for (int nt = 0; nt < 8; nt++) {
                uint32_t b0 = Vs[(kk * 8 + tq) * 68 + nt * 8 + gq];
                uint32_t b1 = Vs[(kk * 8 + tq + 4) * 68 + nt * 8 + gq];
                mma_tf32(O[nt], a0, a1, a2, a3, b0, b1);
            }
        }
    }

    // ---- finalize ----
    l0 += __shfl_xor_sync(0xffffffff, l0, 1);
    l0 += __shfl_xor_sync(0xffffffff, l0, 2);
    l1 += __shfl_xor_sync(0xffffffff, l1, 1);
    l1 += __shfl_xor_sync(0xffffffff, l1, 2);
    float inv0 = 1.f / l0;
    float inv1 = 1.f / l1;

    const int bb = bh >> 4;
    const int h = bh & 15;
    const int r0g = qb + wrow + gq;
    #pragma unroll
    for (int nt = 0; nt < 8; nt++) {
        int col = h * 64 + nt * 8 + 2 * tq;
        float2 w0; w0.x = O[nt][0] * inv0; w0.y = O[nt][1] * inv0;
        float2 w1; w1.x = O[nt][2] * inv1; w1.y = O[nt][3] * inv1;
        *(float2*)(g_ao + (size_t)(bb * Tn + r0g) * Dn + col) = w0;
        *(float2*)(g_ao + (size_t)(bb * Tn + r0g + 8) * Dn + col) = w1;
    }
}

// ---------------------------------------------------------------------------
extern "C" void kernel_launch(void* const* d_in, const int* in_sizes, int n_in,
                              void* d_out, int out_size)
{
    const float* x      = (const float*)d_in[0];
    const float* w_kqv  = (const float*)d_in[1];
    const float* w_proj = (const float*)d_in[2];
    const float* b_proj = (const float*)d_in[3];
    float* out = (float*)d_out;

    cudaFuncSetAttribute(attn_mma, cudaFuncAttributeMaxDynamicSharedMemorySize, SMEM_ATTN);

    rope_init<<<64, 1024>>>();

    dim3 g1(3*Dn/128, Mrows/128);   // 24 x 64
    gemm_tf32<0><<<g1, 256>>>(x, w_kqv, nullptr, nullptr);

    dim3 g2(Tn/128, Bn*Hn);         // 16 x 64
    attn_mma<<<g2, 256, SMEM_ATTN>>>();

    dim3 g3(Dn/128, Mrows/128);     // 8 x 64
    gemm_tf32<1><<<g3, 256>>>(nullptr, w_proj, b_proj, out);
}

// round 6
// speedup vs baseline: 1.3189x; 1.3189x over previous
#include <cuda_runtime.h>
#include <math.h>
#include <stdint.h>

// Problem constants
#define Bn 4
#define Tn 2048
#define Dn 1024
#define Hn 16
#define HS 64
#define Mrows (Bn*Tn)          // 8192

// Scratch (device globals; no runtime allocation allowed)
__device__ float g_q[(size_t)Bn*Hn*Tn*HS];   // [B,H,T,hs] rope'd, scaled, tf32-rounded
__device__ float g_k[(size_t)Bn*Hn*Tn*HS];   // [B,H,T,hs] rope'd, tf32-rounded
__device__ float g_v[(size_t)Bn*Hn*Tn*HS];   // [B,H,T,hs] tf32-rounded
__device__ float g_ao[(size_t)Bn*Tn*Dn];     // attention output [B*T, D], tf32-rounded
__device__ float2 g_rope[Tn*32];             // (cos, sin) table
// tf32-rounded operand copies (enable raw cp.async staging in GEMMs)
__device__ float g_xt[(size_t)Mrows*Dn];
__device__ float g_wk[(size_t)3*Dn*Dn];
__device__ float g_wp[(size_t)Dn*Dn];

// ---------------------------------------------------------------------------
// helpers
// ---------------------------------------------------------------------------
__device__ __forceinline__ uint32_t f2tf(float x) {
    uint32_t u;
    asm("cvt.rna.tf32.f32 %0, %1;" : "=r"(u) : "f"(x));
    return u;
}

__device__ __forceinline__ float ex2(float x) {
    float y;
    asm("ex2.approx.f32 %0, %1;" : "=f"(y) : "f"(x));
    return y;
}

__device__ __forceinline__ void mma_tf32(float c[4],
                                         uint32_t a0, uint32_t a1, uint32_t a2, uint32_t a3,
                                         uint32_t b0, uint32_t b1)
{
    asm volatile(
        "mma.sync.aligned.m16n8k8.row.col.f32.tf32.tf32.f32 "
        "{%0,%1,%2,%3}, {%4,%5,%6,%7}, {%8,%9}, {%0,%1,%2,%3};\n"
        : "+f"(c[0]), "+f"(c[1]), "+f"(c[2]), "+f"(c[3])
        : "r"(a0), "r"(a1), "r"(a2), "r"(a3), "r"(b0), "r"(b1));
}

__device__ __forceinline__ void cpa16(uint32_t dst_smem, const void* src) {
    asm volatile("cp.async.cg.shared.global [%0], [%1], 16;" :: "r"(dst_smem), "l"(src));
}
#define CP_COMMIT()  asm volatile("cp.async.commit_group;")
#define CP_WAIT(n)   asm volatile("cp.async.wait_group " #n ";")

__device__ __forceinline__ int sw_idx(int row, int k) {
    return row * 16 + (k ^ (((row >> 1) & 3) << 2));
}

// ---------------------------------------------------------------------------
// RoPE table init
// ---------------------------------------------------------------------------
__global__ void rope_init()
{
    int idx = blockIdx.x * blockDim.x + threadIdx.x;  // 0..65535
    int t = idx >> 5;
    int i = idx & 31;
    float theta = powf(10000.0f, (float)i * (-2.0f / 64.0f));
    float ang = (float)t * theta;
    float sn, cs;
    sincosf(ang, &sn, &cs);
    g_rope[idx] = make_float2(cs, sn);
}

// ---------------------------------------------------------------------------
// tf32-round a buffer into one of the operand copies (sel: 0=x,1=w_kqv,2=w_proj)
// ---------------------------------------------------------------------------
__global__ void cvt_tf32(int sel, const float* __restrict__ in, int n4)
{
    float* out = (sel == 0) ? g_xt : (sel == 1) ? g_wk : g_wp;
    int i = blockIdx.x * blockDim.x + threadIdx.x;
    if (i < n4) {
        float4 v = ((const float4*)in)[i];
        uint4 u;
        u.x = f2tf(v.x); u.y = f2tf(v.y); u.z = f2tf(v.z); u.w = f2tf(v.w);
        ((uint4*)out)[i] = u;
    }
}

// ---------------------------------------------------------------------------
// tf32 tensor-core GEMM: C[M,N] = A[M,1024] @ W[N,1024]^T (row-major)
// Block 128x128, BK=16, 256 threads = 8 warps (2x4), warp tile 64x32.
// 3-stage cp.async pipeline, ONE __syncthreads per k-tile.
// Operands are pre-rounded to tf32 (raw bit copies into smem).
// MODE 0: A=g_xt, W=g_wk, QKV epilogue (table-RoPE scatter; tf32-rounded out)
// MODE 1: A=g_ao, W=g_wp, proj epilogue (bias add -> out)
// ---------------------------------------------------------------------------
template<int MODE>
__global__ void __launch_bounds__(256) gemm_tf32(const float* __restrict__ bias,
                                                 float* __restrict__ out)
{
    extern __shared__ __align__(16) uint32_t gsm[];
    uint32_t* As = gsm;            // [3][2048]
    uint32_t* Ws = gsm + 3 * 2048; // [3][2048]

    const int m0 = blockIdx.y * 128;
    const int n0 = blockIdx.x * 128;
    const int tid = threadIdx.x;
    const int wid = tid >> 5;
    const int lane = tid & 31;
    const int wm = wid >> 2;
    const int wn = wid & 3;
    const int gq = lane >> 2;
    const int tq = lane & 3;

    const int lrow = tid >> 2;
    const int lkc = (tid & 3) << 2;
    const int sw0 = sw_idx(lrow, lkc);
    const int sw1 = sw0 + 64 * 16;

    const float* Abase = (MODE == 1) ? (const float*)g_ao : (const float*)g_xt;
    const float* Wbase = (MODE == 1) ? (const float*)g_wp : (const float*)g_wk;
    const float* Ap0 = Abase + (size_t)(m0 + lrow) * 1024 + lkc;
    const float* Ap1 = Ap0 + (size_t)64 * 1024;
    const float* Wp0 = Wbase + (size_t)(n0 + lrow) * 1024 + lkc;
    const float* Wp1 = Wp0 + (size_t)64 * 1024;

    const uint32_t sA = (uint32_t)__cvta_generic_to_shared(As);
    const uint32_t sW = (uint32_t)__cvta_generic_to_shared(Ws);

    float acc[4][4][4];
    #pragma unroll
    for (int mt = 0; mt < 4; mt++)
        #pragma unroll
        for (int nt = 0; nt < 4; nt++)
            #pragma unroll
            for (int r = 0; r < 4; r++) acc[mt][nt][r] = 0.f;

    // prologue: issue tiles 0 and 1
    #pragma unroll
    for (int p = 0; p < 2; p++) {
        cpa16(sA + (p * 2048 + sw0) * 4, Ap0 + p * 16);
        cpa16(sA + (p * 2048 + sw1) * 4, Ap1 + p * 16);
        cpa16(sW + (p * 2048 + sw0) * 4, Wp0 + p * 16);
        cpa16(sW + (p * 2048 + sw1) * 4, Wp1 + p * 16);
        CP_COMMIT();
    }

    int st = 0;
    for (int kt = 0; kt < 64; kt++) {
        if (kt < 63) { CP_WAIT(1); } else { CP_WAIT(0); }
        __syncthreads();   // tile kt visible to all; all done reading the buffer reissued below

        if (kt + 2 < 64) {
            int stn = st + 2; if (stn >= 3) stn -= 3;
            int koff = (kt + 2) * 16;
            cpa16(sA + (stn * 2048 + sw0) * 4, Ap0 + koff);
            cpa16(sA + (stn * 2048 + sw1) * 4, Ap1 + koff);
            cpa16(sW + (stn * 2048 + sw0) * 4, Wp0 + koff);
            cpa16(sW + (stn * 2048 + sw1) * 4, Wp1 + koff);
            CP_COMMIT();
        }

        const uint32_t* Acur = As + st * 2048;
        const uint32_t* Wcur = Ws + st * 2048;
        #pragma unroll
        for (int ks = 0; ks < 2; ks++) {
            uint32_t af[4][4];
            uint32_t bf[4][2];
            #pragma unroll
            for (int mt = 0; mt < 4; mt++) {
                int mb = wm * 64 + mt * 16 + gq;
                int swm = ((mb >> 1) & 3) << 2;
                int klo = ks * 8 + tq;
                af[mt][0] = Acur[mb * 16 + (klo ^ swm)];
                af[mt][1] = Acur[(mb + 8) * 16 + (klo ^ swm)];
                af[mt][2] = Acur[mb * 16 + ((klo + 4) ^ swm)];
                af[mt][3] = Acur[(mb + 8) * 16 + ((klo + 4) ^ swm)];
            }
            #pragma unroll
            for (int nt = 0; nt < 4; nt++) {
                int nb = wn * 32 + nt * 8 + gq;
                int swn = ((nb >> 1) & 3) << 2;
                int klo = ks * 8 + tq;
                bf[nt][0] = Wcur[nb * 16 + (klo ^ swn)];
                bf[nt][1] = Wcur[nb * 16 + ((klo + 4) ^ swn)];
            }
            #pragma unroll
            for (int mt = 0; mt < 4; mt++)
                #pragma unroll
                for (int nt = 0; nt < 4; nt++)
                    mma_tf32(acc[mt][nt], af[mt][0], af[mt][1], af[mt][2], af[mt][3],
                             bf[nt][0], bf[nt][1]);
        }
        st = (st == 2) ? 0 : st + 1;
    }

    if (MODE == 0) {
        const float QSC = 0.125f * 1.4426950408889634f;  // scale * log2(e)
        #pragma unroll
        for (int mt = 0; mt < 4; mt++) {
            #pragma unroll
            for (int r = 0; r < 2; r++) {
                int m = m0 + wm * 64 + mt * 16 + gq + r * 8;
                int bb = m >> 11;
                int tt = m & 2047;
                #pragma unroll
                for (int nt = 0; nt < 4; nt++) {
                    int col = n0 + wn * 32 + nt * 8 + 2 * tq;
                    int which = col >> 10;
                    int rem = col & 1023;
                    int h = rem >> 6;
                    int d = rem & 63;
                    size_t off = ((size_t)((bb * Hn + h) * Tn + tt)) * HS + d;
                    float e = acc[mt][nt][r * 2 + 0];
                    float o = acc[mt][nt][r * 2 + 1];
                    if (which == 2) {
                        float2 v2;
                        v2.x = __uint_as_float(f2tf(e));
                        v2.y = __uint_as_float(f2tf(o));
                        *(float2*)(g_v + off) = v2;
                    } else {
                        float2 cs = g_rope[tt * 32 + (d >> 1)];
                        float t1 = e * cs.x - o * cs.y;
                        float t2 = e * cs.y + o * cs.x;
                        float2 v2;
                        if (which == 0) {
                            v2.x = __uint_as_float(f2tf(t1));
                            v2.y = __uint_as_float(f2tf(t2));
                            *(float2*)(g_k + off) = v2;
                        } else {
                            v2.x = __uint_as_float(f2tf(t1 * QSC));
                            v2.y = __uint_as_float(f2tf(t2 * QSC));
                            *(float2*)(g_q + off) = v2;
                        }
                    }
                }
            }
        }
    } else {
        #pragma unroll
        for (int mt = 0; mt < 4; mt++) {
            #pragma unroll
            for (int r = 0; r < 2; r++) {
                int m = m0 + wm * 64 + mt * 16 + gq + r * 8;
                #pragma unroll
                for (int nt = 0; nt < 4; nt++) {
                    int col = n0 + wn * 32 + nt * 8 + 2 * tq;
                    float2 v2;
                    v2.x = acc[mt][nt][r * 2 + 0] + bias[col + 0];
                    v2.y = acc[mt][nt][r * 2 + 1] + bias[col + 1];
                    *(float2*)(out + (size_t)m * 1024 + col) = v2;
                }
            }
        }
    }
}

// ---------------------------------------------------------------------------
// Tensor-core causal flash attention (tf32 mma.sync), m32 warp tiles.
// Block: 128 q-rows, 4 warps x m32, 2 CTAs/SM. 2-stage cp.async K/V pipeline,
// ONE __syncthreads per tile. Vs stride 72 (conflict-free V fragment loads).
// grid = (16, 64); heavy (long) q-blocks launch first.
// ---------------------------------------------------------------------------
#define KS_ST 4352   // 64*68 words per K stage
#define VS_ST 4608   // 64*72 words per V stage
#define SMEM_ATTN ((2*KS_ST + 2*VS_ST + 128*68) * 4)

__global__ void __launch_bounds__(128, 2) attn_mma()
{
    extern __shared__ __align__(16) char smraw[];
    uint32_t* KsB = (uint32_t*)smraw;       // [2][64*68]
    uint32_t* VsB = KsB + 2 * KS_ST;        // [2][64*72]
    float*    Ps  = (float*)(VsB + 2 * VS_ST);  // [128*68] (Q staging, then P)

    const int bh = blockIdx.y;
    const int qt = gridDim.x - 1 - blockIdx.x;   // heavy blocks first
    const int tid = threadIdx.x;
    const int wid = tid >> 5;      // 0..3
    const int lane = tid & 31;
    const int gq = lane >> 2;
    const int tq = lane & 3;
    const int qb = qt * 128;
    const int wrow = wid * 32;

    const size_t base = (size_t)bh * Tn * HS;
    const float* Qp = g_q + base;
    const float* Kp = g_k + base;
    const float* Vp = g_v + base;

    const uint32_t sK = (uint32_t)__cvta_generic_to_shared(KsB);
    const uint32_t sV = (uint32_t)__cvta_generic_to_shared(VsB);

    // issue K/V tile kt into stage st (8 x 16B each per thread)
    const int srr = tid >> 4;
    const int scc = (tid & 15) << 2;

    // prologue: tile 0 -> stage 0
    #pragma unroll
    for (int l = 0; l < 8; l++) {
        int rr = srr + l * 8;
        cpa16(sK + (0 * KS_ST + rr * 68 + scc) * 4, Kp + (size_t)rr * HS + scc);
        cpa16(sV + (0 * VS_ST + rr * 72 + scc) * 4, Vp + (size_t)rr * HS + scc);
    }
    CP_COMMIT();

    // stage Q tile into Ps
    #pragma unroll
    for (int l = 0; l < 16; l++) {
        int idx = tid + l * 128;
        int rr = idx >> 4;
        int cc = (idx & 15) << 2;
        float4 v = *(const float4*)(Qp + (size_t)(qb + rr) * HS + cc);
        *(float4*)&Ps[rr * 68 + cc] = v;
    }
    __syncthreads();

    int roff[2][2];
    #pragma unroll
    for (int s = 0; s < 2; s++) {
        roff[s][0] = (wrow + 16 * s + gq) * 68;
        roff[s][1] = (wrow + 16 * s + gq + 8) * 68;
    }

    uint32_t qf[2][8][4];
    #pragma unroll
    for (int s = 0; s < 2; s++)
        #pragma unroll
        for (int kk = 0; kk < 8; kk++) {
            qf[s][kk][0] = __float_as_uint(Ps[roff[s][0] + kk * 8 + tq]);
            qf[s][kk][1] = __float_as_uint(Ps[roff[s][1] + kk * 8 + tq]);
            qf[s][kk][2] = __float_as_uint(Ps[roff[s][0] + kk * 8 + tq + 4]);
            qf[s][kk][3] = __float_as_uint(Ps[roff[s][1] + kk * 8 + tq + 4]);
        }

    float O[2][8][4];
    #pragma unroll
    for (int s = 0; s < 2; s++)
        #pragma unroll
        for (int nt = 0; nt < 8; nt++)
            #pragma unroll
            for (int r = 0; r < 4; r++) O[s][nt][r] = 0.f;
    float mrow[2][2], lrow_[2][2];
    #pragma unroll
    for (int s = 0; s < 2; s++) {
        mrow[s][0] = -INFINITY; mrow[s][1] = -INFINITY;
        lrow_[s][0] = 0.f;      lrow_[s][1] = 0.f;
    }

    const int ntiles = 2 * qt + 2;
    int st = 0;
    for (int kt = 0; kt < ntiles; kt++) {
        const int k0 = kt * 64;
        CP_WAIT(0);        // tile kt landed (this thread's copies)
        __syncthreads();   // visible to all; all warps done with stage st^1

        if (kt + 1 < ntiles) {
            int stn = st ^ 1;
            const float* Kn = Kp + (size_t)(k0 + 64) * HS;
            const float* Vn = Vp + (size_t)(k0 + 64) * HS;
            #pragma unroll
            for (int l = 0; l < 8; l++) {
                int rr = srr + l * 8;
                cpa16(sK + (stn * KS_ST + rr * 68 + scc) * 4, Kn + (size_t)rr * HS + scc);
                cpa16(sV + (stn * VS_ST + rr * 72 + scc) * 4, Vn + (size_t)rr * HS + scc);
            }
            CP_COMMIT();
        }

        if (k0 <= qb + wrow + 31) {
            const uint32_t* Ks = KsB + st * KS_ST;
            const uint32_t* Vs = VsB + st * VS_ST;

            // ---- S = Q K^T ----
            float S[2][8][4];
            #pragma unroll
            for (int s = 0; s < 2; s++)
                #pragma unroll
                for (int nt = 0; nt < 8; nt++)
                    #pragma unroll
                    for (int r = 0; r < 4; r++) S[s][nt][r] = 0.f;

            #pragma unroll
            for (int kk = 0; kk < 8; kk++) {
                #pragma unroll
                for (int nt = 0; nt < 8; nt++) {
                    uint32_t b0 = Ks[(nt * 8 + gq) * 68 + kk * 8 + tq];
                    uint32_t b1 = Ks[(nt * 8 + gq) * 68 + kk * 8 + tq + 4];
                    mma_tf32(S[0][nt], qf[0][kk][0], qf[0][kk][1], qf[0][kk][2], qf[0][kk][3], b0, b1);
                    mma_tf32(S[1][nt], qf[1][kk][0], qf[1][kk][1], qf[1][kk][2], qf[1][kk][3], b0, b1);
                }
            }

            // ---- causal mask (diagonal region only) ----
            if (k0 + 63 > qb + wrow) {
                #pragma unroll
                for (int s = 0; s < 2; s++) {
                    int row0 = qb + wrow + 16 * s + gq;
                    #pragma unroll
                    for (int nt = 0; nt < 8; nt++) {
                        int col = k0 + nt * 8 + 2 * tq;
                        if (col     > row0)     S[s][nt][0] = -INFINITY;
                        if (col + 1 > row0)     S[s][nt][1] = -INFINITY;
                        if (col     > row0 + 8) S[s][nt][2] = -INFINITY;
                        if (col + 1 > row0 + 8) S[s][nt][3] = -INFINITY;
                    }
                }
            }

            // ---- online softmax + P store ----
            __syncwarp();
            #pragma unroll
            for (int s = 0; s < 2; s++) {
                float cm0 = -INFINITY, cm1 = -INFINITY;
                #pragma unroll
                for (int nt = 0; nt < 8; nt++) {
                    cm0 = fmaxf(cm0, fmaxf(S[s][nt][0], S[s][nt][1]));
                    cm1 = fmaxf(cm1, fmaxf(S[s][nt][2], S[s][nt][3]));
                }
                cm0 = fmaxf(cm0, __shfl_xor_sync(0xffffffff, cm0, 1));
                cm0 = fmaxf(cm0, __shfl_xor_sync(0xffffffff, cm0, 2));
                cm1 = fmaxf(cm1, __shfl_xor_sync(0xffffffff, cm1, 1));
                cm1 = fmaxf(cm1, __shfl_xor_sync(0xffffffff, cm1, 2));

                float mn0 = fmaxf(mrow[s][0], cm0);
                float mn1 = fmaxf(mrow[s][1], cm1);
                float c0 = ex2(mrow[s][0] - mn0);
                float c1 = ex2(mrow[s][1] - mn1);
                lrow_[s][0] *= c0; lrow_[s][1] *= c1;
                #pragma unroll
                for (int nt = 0; nt < 8; nt++) {
                    O[s][nt][0] *= c0; O[s][nt][1] *= c0;
                    O[s][nt][2] *= c1; O[s][nt][3] *= c1;
                }
                mrow[s][0] = mn0; mrow[s][1] = mn1;

                #pragma unroll
                for (int nt = 0; nt < 8; nt++) {
                    float p0 = ex2(S[s][nt][0] - mn0);
                    float p1 = ex2(S[s][nt][1] - mn0);
                    float p2 = ex2(S[s][nt][2] - mn1);
                    float p3 = ex2(S[s][nt][3] - mn1);
                    lrow_[s][0] += p0 + p1;
                    lrow_[s][1] += p2 + p3;
                    float2 w0; w0.x = __uint_as_float(f2tf(p0)); w0.y = __uint_as_float(f2tf(p1));
                    float2 w1; w1.x = __uint_as_float(f2tf(p2)); w1.y = __uint_as_float(f2tf(p3));
                    *(float2*)&Ps[roff[s][0] + nt * 8 + 2 * tq] = w0;
                    *(float2*)&Ps[roff[s][1] + nt * 8 + 2 * tq] = w1;
                }
            }
            __syncwarp();

            // ---- O += P V ----
            #pragma unroll
            for (int kk = 0; kk < 8; kk++) {
                uint32_t a[2][4];
                #pragma unroll
                for (int s = 0; s < 2; s++) {
                    a[s][0] = __float_as_uint(Ps[roff[s][0] + kk * 8 + tq]);
                    a[s][1] = __float_as_uint(Ps[roff[s][1] + kk * 8 + tq]);
                    a[s][2] = __float_as_uint(Ps[roff[s][0] + kk * 8 + tq + 4]);
                    a[s][3] = __float_as_uint(Ps[roff[s][1] + kk * 8 + tq + 4]);
                }
                #pragma unroll
                for (int nt = 0; nt < 8; nt++) {
                    uint32_t b0 = Vs[(kk * 8 + tq) * 72 + nt * 8 + gq];
                    uint32_t b1 = Vs[(kk * 8 + tq + 4) * 72 + nt * 8 + gq];
                    mma_tf32(O[0][nt], a[0][0], a[0][1], a[0][2], a[0][3], b0, b1);
                    mma_tf32(O[1][nt], a[1][0], a[1][1], a[1][2], a[1][3], b0, b1);
                }
            }
        }
        st ^= 1;
    }

    // ---- finalize (tf32-round for the cp.async proj GEMM) ----
    const int bb = bh >> 4;
    const int h = bh & 15;
    #pragma unroll
    for (int s = 0; s < 2; s++) {
        float l0 = lrow_[s][0], l1 = lrow_[s][1];
        l0 += __shfl_xor_sync(0xffffffff, l0, 1);
        l0 += __shfl_xor_sync(0xffffffff, l0, 2);
        l1 += __shfl_xor_sync(0xffffffff, l1, 1);
        l1 += __shfl_xor_sync(0xffffffff, l1, 2);
        float inv0 = 1.f / l0;
        float inv1 = 1.f / l1;
        int r0g = qb + wrow + 16 * s + gq;
        #pragma unroll
        for (int nt = 0; nt < 8; nt++) {
            int col = h * 64 + nt * 8 + 2 * tq;
            float2 w0, w1;
            w0.x = __uint_as_float(f2tf(O[s][nt][0] * inv0));
            w0.y = __uint_as_float(f2tf(O[s][nt][1] * inv0));
            w1.x = __uint_as_float(f2tf(O[s][nt][2] * inv1));
            w1.y = __uint_as_float(f2tf(O[s][nt][3] * inv1));
            *(float2*)(g_ao + (size_t)(bb * Tn + r0g) * Dn + col) = w0;
            *(float2*)(g_ao + (size_t)(bb * Tn + r0g + 8) * Dn + col) = w1;
        }
    }
}

// ---------------------------------------------------------------------------
extern "C" void kernel_launch(void* const* d_in, const int* in_sizes, int n_in,
                              void* d_out, int out_size)
{
    const float* x      = (const float*)d_in[0];
    const float* w_kqv  = (const float*)d_in[1];
    const float* w_proj = (const float*)d_in[2];
    const float* b_proj = (const float*)d_in[3];
    float* out = (float*)d_out;

    cudaFuncSetAttribute(attn_mma, cudaFuncAttributeMaxDynamicSharedMemorySize, SMEM_ATTN);
    cudaFuncSetAttribute(gemm_tf32<0>, cudaFuncAttributeMaxDynamicSharedMemorySize, 49152);
    cudaFuncSetAttribute(gemm_tf32<1>, cudaFuncAttributeMaxDynamicSharedMemorySize, 49152);

    rope_init<<<64, 1024>>>();
    cvt_tf32<<<8192, 256>>>(0, x,      Mrows*Dn/4);   // 2097152
    cvt_tf32<<<3072, 256>>>(1, w_kqv,  3*Dn*Dn/4);    // 786432
    cvt_tf32<<<1024, 256>>>(2, w_proj, Dn*Dn/4);      // 262144

    dim3 g1(3*Dn/128, Mrows/128);   // 24 x 64
    gemm_tf32<0><<<g1, 256, 49152>>>(nullptr, nullptr);

    dim3 g2(Tn/128, Bn*Hn);         // 16 x 64
    attn_mma<<<g2, 128, SMEM_ATTN>>>();

    dim3 g3(Dn/128, Mrows/128);     // 8 x 64
    gemm_tf32<1><<<g3, 256, 49152>>>(b_proj, out);
}

// round 7
// speedup vs baseline: 1.3607x; 1.0317x over previous
#include <cuda_runtime.h>
#include <math.h>
#include <stdint.h>

// Problem constants
#define Bn 4
#define Tn 2048
#define Dn 1024
#define Hn 16
#define HS 64
#define Mrows (Bn*Tn)          // 8192

// Scratch (device globals; no runtime allocation allowed)
__device__ float g_q[(size_t)Bn*Hn*Tn*HS];   // [B,H,T,hs] rope'd, scaled, tf32-rounded
__device__ float g_k[(size_t)Bn*Hn*Tn*HS];   // [B,H,T,hs] rope'd, tf32-rounded
__device__ float g_v[(size_t)Bn*Hn*Tn*HS];   // [B,H,T,hs] tf32-rounded
__device__ float g_ao[(size_t)Bn*Tn*Dn];     // attention out, PACKED fragment-major tiles
__device__ float2 g_rope[Tn*32];             // (cos, sin) table
// fragment-major packed operands (tf32-rounded)
__device__ float g_xt[(size_t)Mrows*Dn];     // A-pack  [64 mtile][64 ktile][2048]
__device__ float g_wk[(size_t)3*Dn*Dn];      // B-pack  [24 ntile][64 ktile][2048]
__device__ float g_wp[(size_t)Dn*Dn];        // B-pack  [ 8 ntile][64 ktile][2048]

// ---------------------------------------------------------------------------
// helpers
// ---------------------------------------------------------------------------
__device__ __forceinline__ uint32_t f2tf(float x) {
    uint32_t u;
    asm("cvt.rna.tf32.f32 %0, %1;" : "=r"(u) : "f"(x));
    return u;
}

__device__ __forceinline__ float ex2(float x) {
    float y;
    asm("ex2.approx.f32 %0, %1;" : "=f"(y) : "f"(x));
    return y;
}

__device__ __forceinline__ void mma_tf32(float c[4],
                                         uint32_t a0, uint32_t a1, uint32_t a2, uint32_t a3,
                                         uint32_t b0, uint32_t b1)
{
    asm volatile(
        "mma.sync.aligned.m16n8k8.row.col.f32.tf32.tf32.f32 "
        "{%0,%1,%2,%3}, {%4,%5,%6,%7}, {%8,%9}, {%0,%1,%2,%3};\n"
        : "+f"(c[0]), "+f"(c[1]), "+f"(c[2]), "+f"(c[3])
        : "r"(a0), "r"(a1), "r"(a2), "r"(a3), "r"(b0), "r"(b1));
}

__device__ __forceinline__ void cpa16(uint32_t dst_smem, const void* src) {
    asm volatile("cp.async.cg.shared.global [%0], [%1], 16;" :: "r"(dst_smem), "l"(src));
}
#define CP_COMMIT()  asm volatile("cp.async.commit_group;")
#define CP_WAIT(n)   asm volatile("cp.async.wait_group " #n ";")

// packed word offset within a 128x16 tile, A-operand style (4-word frags)
__device__ __forceinline__ int offA(int m, int k) {
    return ((((( (m >> 6) * 4 + ((m >> 4) & 3)) * 2 + (k >> 3)) * 8 + (m & 7)) * 4
            + (k & 3)) * 4) + ((k >> 2) & 1) * 2 + ((m >> 3) & 1);
}
// packed word offset, B-operand style (2-word frags)
__device__ __forceinline__ int offB(int n, int k) {
    return ((((( (n >> 5) * 4 + ((n >> 3) & 3)) * 2 + (k >> 3)) * 8 + (n & 7)) * 4
            + (k & 3)) * 2) + ((k >> 2) & 1);
}

// ---------------------------------------------------------------------------
// RoPE table init
// ---------------------------------------------------------------------------
__global__ void rope_init()
{
    int idx = blockIdx.x * blockDim.x + threadIdx.x;  // 0..65535
    int t = idx >> 5;
    int i = idx & 31;
    float theta = powf(10000.0f, (float)i * (-2.0f / 64.0f));
    float ang = (float)t * theta;
    float sn, cs;
    sincosf(ang, &sn, &cs);
    g_rope[idx] = make_float2(cs, sn);
}

// ---------------------------------------------------------------------------
// Pack src[M,1024] (row-major fp32) into fragment-major tf32 tiles.
// sel: 0 -> g_xt (A-pack), 1 -> g_wk (B-pack), 2 -> g_wp (B-pack)
// Block handles 128 rows x 64 k-cols (4 tiles); grid = (16, M/128).
// ---------------------------------------------------------------------------
__global__ void __launch_bounds__(256) pack_op(int sel, const float* __restrict__ src)
{
    __shared__ float sm[8192];
    const int k0 = blockIdx.x * 64;
    const int m0 = blockIdx.y * 128;
    const int tid = threadIdx.x;
    float* dst = (sel == 0) ? g_xt : (sel == 1) ? g_wk : g_wp;

    #pragma unroll
    for (int l = 0; l < 8; l++) {
        int idx = tid + l * 256;       // 2048 float4 slots
        int row = idx >> 4;
        int c4 = (idx & 15) * 4;
        float4 v = *(const float4*)(src + (size_t)(m0 + row) * 1024 + k0 + c4);
        float e[4] = {v.x, v.y, v.z, v.w};
        #pragma unroll
        for (int j = 0; j < 4; j++) {
            int kc = c4 + j;
            int ktl = kc >> 4;
            int k16 = kc & 15;
            int off = (sel == 0) ? offA(row, k16) : offB(row, k16);
            sm[ktl * 2048 + off] = __uint_as_float(f2tf(e[j]));
        }
    }
    __syncthreads();
    size_t gb = ((size_t)blockIdx.y * 64 + blockIdx.x * 4) * 2048;
    #pragma unroll
    for (int l = 0; l < 8; l++) {
        int i = tid + l * 256;
        *(float4*)(dst + gb + (size_t)i * 4) = *(float4*)(sm + i * 4);
    }
}

// ---------------------------------------------------------------------------
// tf32 tensor-core GEMM on PACKED operands: C[M,N] = A @ W^T, K=1024.
// Block 128x128, BK=16, 256 threads = 8 warps (2x4), warp tile 64x32.
// 3-stage cp.async pipeline (pure linear tile copies), one barrier per k-tile.
// Fragment loads: A = LDS.128, B = LDS.64 (4+4 per ks).
// MODE 0: A=g_xt, W=g_wk, QKV epilogue (RoPE scatter, tf32-rounded out)
// MODE 1: A=g_ao (packed by attention), W=g_wp, proj epilogue (bias -> out)
// ---------------------------------------------------------------------------
template<int MODE>
__global__ void __launch_bounds__(256) gemm_tf32(const float* __restrict__ bias,
                                                 float* __restrict__ out)
{
    extern __shared__ __align__(16) uint32_t gsm[];
    uint32_t* As = gsm;            // [3][2048]
    uint32_t* Ws = gsm + 3 * 2048; // [3][2048]

    const int m0 = blockIdx.y * 128;
    const int n0 = blockIdx.x * 128;
    const int tid = threadIdx.x;
    const int wid = tid >> 5;
    const int lane = tid & 31;
    const int wm = wid >> 2;
    const int wn = wid & 3;
    const int gq = lane >> 2;
    const int tq = lane & 3;

    const float* Abase = (MODE == 1) ? (const float*)g_ao : (const float*)g_xt;
    const float* Wbase = (MODE == 1) ? (const float*)g_wp : (const float*)g_wk;
    const float* Atiles = Abase + (size_t)blockIdx.y * 64 * 2048;
    const float* Wtiles = Wbase + (size_t)blockIdx.x * 64 * 2048;

    const uint32_t sA = (uint32_t)__cvta_generic_to_shared(As);
    const uint32_t sW = (uint32_t)__cvta_generic_to_shared(Ws);

    float acc[4][4][4];
    #pragma unroll
    for (int mt = 0; mt < 4; mt++)
        #pragma unroll
        for (int nt = 0; nt < 4; nt++)
            #pragma unroll
            for (int r = 0; r < 4; r++) acc[mt][nt][r] = 0.f;

    // prologue: issue tiles 0 and 1 (linear 2048-word copies; 8 words/thread)
    #pragma unroll
    for (int p = 0; p < 2; p++) {
        cpa16(sA + (p * 2048 + tid * 8 + 0) * 4, Atiles + (size_t)p * 2048 + tid * 8 + 0);
        cpa16(sA + (p * 2048 + tid * 8 + 4) * 4, Atiles + (size_t)p * 2048 + tid * 8 + 4);
        cpa16(sW + (p * 2048 + tid * 8 + 0) * 4, Wtiles + (size_t)p * 2048 + tid * 8 + 0);
        cpa16(sW + (p * 2048 + tid * 8 + 4) * 4, Wtiles + (size_t)p * 2048 + tid * 8 + 4);
        CP_COMMIT();
    }

    int st = 0;
    for (int kt = 0; kt < 64; kt++) {
        if (kt < 63) { CP_WAIT(1); } else { CP_WAIT(0); }
        __syncthreads();

        if (kt + 2 < 64) {
            int stn = st + 2; if (stn >= 3) stn -= 3;
            const float* At = Atiles + (size_t)(kt + 2) * 2048;
            const float* Wt = Wtiles + (size_t)(kt + 2) * 2048;
            cpa16(sA + (stn * 2048 + tid * 8 + 0) * 4, At + tid * 8 + 0);
            cpa16(sA + (stn * 2048 + tid * 8 + 4) * 4, At + tid * 8 + 4);
            cpa16(sW + (stn * 2048 + tid * 8 + 0) * 4, Wt + tid * 8 + 0);
            cpa16(sW + (stn * 2048 + tid * 8 + 4) * 4, Wt + tid * 8 + 4);
            CP_COMMIT();
        }

        const uint32_t* Acur = As + st * 2048;
        const uint32_t* Wcur = Ws + st * 2048;
        #pragma unroll
        for (int ks = 0; ks < 2; ks++) {
            uint4 af[4];
            uint2 bf[4];
            #pragma unroll
            for (int mt = 0; mt < 4; mt++)
                af[mt] = *(const uint4*)&Acur[(((wm * 8 + mt * 2 + ks) * 8 + gq) * 4 + tq) * 4];
            #pragma unroll
            for (int nt = 0; nt < 4; nt++)
                bf[nt] = *(const uint2*)&Wcur[(((wn * 8 + nt * 2 + ks) * 8 + gq) * 4 + tq) * 2];
            #pragma unroll
            for (int mt = 0; mt < 4; mt++)
                #pragma unroll
                for (int nt = 0; nt < 4; nt++)
                    mma_tf32(acc[mt][nt], af[mt].x, af[mt].y, af[mt].z, af[mt].w,
                             bf[nt].x, bf[nt].y);
        }
        st = (st == 2) ? 0 : st + 1;
    }

    if (MODE == 0) {
        const float QSC = 0.125f * 1.4426950408889634f;  // scale * log2(e)
        #pragma unroll
        for (int mt = 0; mt < 4; mt++) {
            #pragma unroll
            for (int r = 0; r < 2; r++) {
                int m = m0 + wm * 64 + mt * 16 + gq + r * 8;
                int bb = m >> 11;
                int tt = m & 2047;
                #pragma unroll
                for (int nt = 0; nt < 4; nt++) {
                    int col = n0 + wn * 32 + nt * 8 + 2 * tq;
                    int which = col >> 10;
                    int rem = col & 1023;
                    int h = rem >> 6;
                    int d = rem & 63;
                    size_t off = ((size_t)((bb * Hn + h) * Tn + tt)) * HS + d;
                    float e = acc[mt][nt][r * 2 + 0];
                    float o = acc[mt][nt][r * 2 + 1];
                    if (which == 2) {
                        float2 v2;
                        v2.x = __uint_as_float(f2tf(e));
                        v2.y = __uint_as_float(f2tf(o));
                        *(float2*)(g_v + off) = v2;
                    } else {
                        float2 cs = g_rope[tt * 32 + (d >> 1)];
                        float t1 = e * cs.x - o * cs.y;
                        float t2 = e * cs.y + o * cs.x;
                        float2 v2;
                        if (which == 0) {
                            v2.x = __uint_as_float(f2tf(t1));
                            v2.y = __uint_as_float(f2tf(t2));
                            *(float2*)(g_k + off) = v2;
                        } else {
                            v2.x = __uint_as_float(f2tf(t1 * QSC));
                            v2.y = __uint_as_float(f2tf(t2 * QSC));
                            *(float2*)(g_q + off) = v2;
                        }
                    }
                }
            }
        }
    } else {
        #pragma unroll
        for (int mt = 0; mt < 4; mt++) {
            #pragma unroll
            for (int r = 0; r < 2; r++) {
                int m = m0 + wm * 64 + mt * 16 + gq + r * 8;
                #pragma unroll
                for (int nt = 0; nt < 4; nt++) {
                    int col = n0 + wn * 32 + nt * 8 + 2 * tq;
                    float2 v2;
                    v2.x = acc[mt][nt][r * 2 + 0] + bias[col + 0];
                    v2.y = acc[mt][nt][r * 2 + 1] + bias[col + 1];
                    *(float2*)(out + (size_t)m * 1024 + col) = v2;
                }
            }
        }
    }
}

// ---------------------------------------------------------------------------
// Tensor-core causal flash attention (tf32 mma.sync), m32 warp tiles.
// Block: 128 q-rows, 4 warps x m32, 2 CTAs/SM. 2-stage cp.async K/V pipeline.
// Epilogue packs output into fragment-major g_ao tiles (via smem, coalesced).
// grid = (16, 64); heavy (long) q-blocks launch first.
// ---------------------------------------------------------------------------
#define KS_ST 4352   // 64*68 words per K stage
#define VS_ST 4608   // 64*72 words per V stage
#define SMEM_ATTN ((2*KS_ST + 2*VS_ST + 128*68) * 4)

__global__ void __launch_bounds__(128, 2) attn_mma()
{
    extern __shared__ __align__(16) char smraw[];
    uint32_t* KsB = (uint32_t*)smraw;       // [2][64*68]
    uint32_t* VsB = KsB + 2 * KS_ST;        // [2][64*72]
    float*    Ps  = (float*)(VsB + 2 * VS_ST);  // [128*68] Q staging / P / O packing

    const int bh = blockIdx.y;
    const int qt = gridDim.x - 1 - blockIdx.x;   // heavy blocks first
    const int tid = threadIdx.x;
    const int wid = tid >> 5;      // 0..3
    const int lane = tid & 31;
    const int gq = lane >> 2;
    const int tq = lane & 3;
    const int qb = qt * 128;
    const int wrow = wid * 32;

    const size_t base = (size_t)bh * Tn * HS;
    const float* Qp = g_q + base;
    const float* Kp = g_k + base;
    const float* Vp = g_v + base;

    const uint32_t sK = (uint32_t)__cvta_generic_to_shared(KsB);
    const uint32_t sV = (uint32_t)__cvta_generic_to_shared(VsB);

    const int srr = tid >> 4;
    const int scc = (tid & 15) << 2;

    // prologue: tile 0 -> stage 0
    #pragma unroll
    for (int l = 0; l < 8; l++) {
        int rr = srr + l * 8;
        cpa16(sK + (0 * KS_ST + rr * 68 + scc) * 4, Kp + (size_t)rr * HS + scc);
        cpa16(sV + (0 * VS_ST + rr * 72 + scc) * 4, Vp + (size_t)rr * HS + scc);
    }
    CP_COMMIT();

    // stage Q tile into Ps
    #pragma unroll
    for (int l = 0; l < 16; l++) {
        int idx = tid + l * 128;
        int rr = idx >> 4;
        int cc = (idx & 15) << 2;
        float4 v = *(const float4*)(Qp + (size_t)(qb + rr) * HS + cc);
        *(float4*)&Ps[rr * 68 + cc] = v;
    }
    __syncthreads();

    int roff[2][2];
    #pragma unroll
    for (int s = 0; s < 2; s++) {
        roff[s][0] = (wrow + 16 * s + gq) * 68;
        roff[s][1] = (wrow + 16 * s + gq + 8) * 68;
    }

    uint32_t qf[2][8][4];
    #pragma unroll
    for (int s = 0; s < 2; s++)
        #pragma unroll
        for (int kk = 0; kk < 8; kk++) {
            qf[s][kk][0] = __float_as_uint(Ps[roff[s][0] + kk * 8 + tq]);
            qf[s][kk][1] = __float_as_uint(Ps[roff[s][1] + kk * 8 + tq]);
            qf[s][kk][2] = __float_as_uint(Ps[roff[s][0] + kk * 8 + tq + 4]);
            qf[s][kk][3] = __float_as_uint(Ps[roff[s][1] + kk * 8 + tq + 4]);
        }

    float O[2][8][4];
    #pragma unroll
    for (int s = 0; s < 2; s++)
        #pragma unroll
        for (int nt = 0; nt < 8; nt++)
            #pragma unroll
            for (int r = 0; r < 4; r++) O[s][nt][r] = 0.f;
    float mrow[2][2], lrow_[2][2];
    #pragma unroll
    for (int s = 0; s < 2; s++) {
        mrow[s][0] = -INFINITY; mrow[s][1] = -INFINITY;
        lrow_[s][0] = 0.f;      lrow_[s][1] = 0.f;
    }

    const int ntiles = 2 * qt + 2;
    int st = 0;
    for (int kt = 0; kt < ntiles; kt++) {
        const int k0 = kt * 64;
        CP_WAIT(0);
        __syncthreads();

        if (kt + 1 < ntiles) {
            int stn = st ^ 1;
            const float* Kn = Kp + (size_t)(k0 + 64) * HS;
            const float* Vn = Vp + (size_t)(k0 + 64) * HS;
            #pragma unroll
            for (int l = 0; l < 8; l++) {
                int rr = srr + l * 8;
                cpa16(sK + (stn * KS_ST + rr * 68 + scc) * 4, Kn + (size_t)rr * HS + scc);
                cpa16(sV + (stn * VS_ST + rr * 72 + scc) * 4, Vn + (size_t)rr * HS + scc);
            }
            CP_COMMIT();
        }

        if (k0 <= qb + wrow + 31) {
            const uint32_t* Ks = KsB + st * KS_ST;
            const uint32_t* Vs = VsB + st * VS_ST;

            float S[2][8][4];
            #pragma unroll
            for (int s = 0; s < 2; s++)
                #pragma unroll
                for (int nt = 0; nt < 8; nt++)
                    #pragma unroll
                    for (int r = 0; r < 4; r++) S[s][nt][r] = 0.f;

            #pragma unroll
            for (int kk = 0; kk < 8; kk++) {
                #pragma unroll
                for (int nt = 0; nt < 8; nt++) {
                    uint32_t b0 = Ks[(nt * 8 + gq) * 68 + kk * 8 + tq];
                    uint32_t b1 = Ks[(nt * 8 + gq) * 68 + kk * 8 + tq + 4];
                    mma_tf32(S[0][nt], qf[0][kk][0], qf[0][kk][1], qf[0][kk][2], qf[0][kk][3], b0, b1);
                    mma_tf32(S[1][nt], qf[1][kk][0], qf[1][kk][1], qf[1][kk][2], qf[1][kk][3], b0, b1);
                }
            }

            if (k0 + 63 > qb + wrow) {
                #pragma unroll
                for (int s = 0; s < 2; s++) {
                    int row0 = qb + wrow + 16 * s + gq;
                    #pragma unroll
                    for (int nt = 0; nt < 8; nt++) {
                        int col = k0 + nt * 8 + 2 * tq;
                        if (col     > row0)     S[s][nt][0] = -INFINITY;
                        if (col + 1 > row0)     S[s][nt][1] = -INFINITY;
                        if (col     > row0 + 8) S[s][nt][2] = -INFINITY;
                        if (col + 1 > row0 + 8) S[s][nt][3] = -INFINITY;
                    }
                }
            }

            __syncwarp();
            #pragma unroll
            for (int s = 0; s < 2; s++) {
                float cm0 = -INFINITY, cm1 = -INFINITY;
                #pragma unroll
                for (int nt = 0; nt < 8; nt++) {
                    cm0 = fmaxf(cm0, fmaxf(S[s][nt][0], S[s][nt][1]));
                    cm1 = fmaxf(cm1, fmaxf(S[s][nt][2], S[s][nt][3]));
                }
                cm0 = fmaxf(cm0, __shfl_xor_sync(0xffffffff, cm0, 1));
                cm0 = fmaxf(cm0, __shfl_xor_sync(0xffffffff, cm0, 2));
                cm1 = fmaxf(cm1, __shfl_xor_sync(0xffffffff, cm1, 1));
                cm1 = fmaxf(cm1, __shfl_xor_sync(0xffffffff, cm1, 2));

                float mn0 = fmaxf(mrow[s][0], cm0);
                float mn1 = fmaxf(mrow[s][1], cm1);
                float c0 = ex2(mrow[s][0] - mn0);
                float c1 = ex2(mrow[s][1] - mn1);
                lrow_[s][0] *= c0; lrow_[s][1] *= c1;
                #pragma unroll
                for (int nt = 0; nt < 8; nt++) {
                    O[s][nt][0] *= c0; O[s][nt][1] *= c0;
                    O[s][nt][2] *= c1; O[s][nt][3] *= c1;
                }
                mrow[s][0] = mn0; mrow[s][1] = mn1;

                #pragma unroll
                for (int nt = 0; nt < 8; nt++) {
                    float p0 = ex2(S[s][nt][0] - mn0);
                    float p1 = ex2(S[s][nt][1] - mn0);
                    float p2 = ex2(S[s][nt][2] - mn1);
                    float p3 = ex2(S[s][nt][3] - mn1);
                    lrow_[s][0] += p0 + p1;
                    lrow_[s][1] += p2 + p3;
                    float2 w0; w0.x = __uint_as_float(f2tf(p0)); w0.y = __uint_as_float(f2tf(p1));
                    float2 w1; w1.x = __uint_as_float(f2tf(p2)); w1.y = __uint_as_float(f2tf(p3));
                    *(float2*)&Ps[roff[s][0] + nt * 8 + 2 * tq] = w0;
                    *(float2*)&Ps[roff[s][1] + nt * 8 + 2 * tq] = w1;
                }
            }
            __syncwarp();

            #pragma unroll
            for (int kk = 0; kk < 8; kk++) {
                uint32_t a[2][4];
                #pragma unroll
                for (int s = 0; s < 2; s++) {
                    a[s][0] = __float_as_uint(Ps[roff[s][0] + kk * 8 + tq]);
                    a[s][1] = __float_as_uint(Ps[roff[s][1] + kk * 8 + tq]);
                    a[s][2] = __float_as_uint(Ps[roff[s][0] + kk * 8 + tq + 4]);
                    a[s][3] = __float_as_uint(Ps[roff[s][1] + kk * 8 + tq + 4]);
                }
                #pragma unroll
                for (int nt = 0; nt < 8; nt++) {
                    uint32_t b0 = Vs[(kk * 8 + tq) * 72 + nt * 8 + gq];
                    uint32_t b1 = Vs[(kk * 8 + tq + 4) * 72 + nt * 8 + gq];
                    mma_tf32(O[0][nt], a[0][0], a[0][1], a[0][2], a[0][3], b0, b1);
                    mma_tf32(O[1][nt], a[1][0], a[1][1], a[1][2], a[1][3], b0, b1);
                }
            }
        }
        st ^= 1;
    }

    // ---- finalize: pack normalized O into fragment-major g_ao tiles ----
    const int bb = bh >> 4;
    const int h = bh & 15;
    __syncthreads();   // everyone done with Ps (P) and mainloop
    #pragma unroll
    for (int s = 0; s < 2; s++) {
        float l0 = lrow_[s][0], l1 = lrow_[s][1];
        l0 += __shfl_xor_sync(0xffffffff, l0, 1);
        l0 += __shfl_xor_sync(0xffffffff, l0, 2);
        l1 += __shfl_xor_sync(0xffffffff, l1, 1);
        l1 += __shfl_xor_sync(0xffffffff, l1, 2);
        float inv[2] = {1.f / l0, 1.f / l1};
        #pragma unroll
        for (int nt = 0; nt < 8; nt++) {
            #pragma unroll
            for (int hi = 0; hi < 2; hi++) {
                int m_local = wrow + 16 * s + hi * 8 + gq;
                #pragma unroll
                for (int e = 0; e < 2; e++) {
                    int c_local = nt * 8 + 2 * tq + e;
                    float val = O[s][nt][hi * 2 + e] * inv[hi];
                    Ps[(c_local >> 4) * 2048 + offA(m_local, c_local & 15)] =
                        __uint_as_float(f2tf(val));
                }
            }
        }
    }
    __syncthreads();
    // coalesced store: 4 tiles = 8192 words, m_tile = bb*16+qt, k_tiles h*4..h*4+3
    {
        float* dst = g_ao + ((size_t)(bb * 16 + qt) * 64 + h * 4) * 2048;
        #pragma unroll
        for (int l = 0; l < 16; l++) {
            int i = tid + l * 128;
            *(float4*)(dst + (size_t)i * 4) = *(float4*)(Ps + i * 4);
        }
    }
}

// ---------------------------------------------------------------------------
extern "C" void kernel_launch(void* const* d_in, const int* in_sizes, int n_in,
                              void* d_out, int out_size)
{
    const float* x      = (const float*)d_in[0];
    const float* w_kqv  = (const float*)d_in[1];
    const float* w_proj = (const float*)d_in[2];
    const float* b_proj = (const float*)d_in[3];
    float* out = (float*)d_out;

    cudaFuncSetAttribute(attn_mma, cudaFuncAttributeMaxDynamicSharedMemorySize, SMEM_ATTN);
    cudaFuncSetAttribute(gemm_tf32<0>, cudaFuncAttributeMaxDynamicSharedMemorySize, 49152);
    cudaFuncSetAttribute(gemm_tf32<1>, cudaFuncAttributeMaxDynamicSharedMemorySize, 49152);

    rope_init<<<64, 1024>>>();
    {
        dim3 gx(16, Mrows/128);      // 16 x 64
        pack_op<<<gx, 256>>>(0, x);
        dim3 gk(16, 3*Dn/128);       // 16 x 24
        pack_op<<<gk, 256>>>(1, w_kqv);
        dim3 gp(16, Dn/128);         // 16 x 8
        pack_op<<<gp, 256>>>(2, w_proj);
    }

    dim3 g1(3*Dn/128, Mrows/128);   // 24 x 64
    gemm_tf32<0><<<g1, 256, 49152>>>(nullptr, nullptr);

    dim3 g2(Tn/128, Bn*Hn);         // 16 x 64
    attn_mma<<<g2, 128, SMEM_ATTN>>>();

    dim3 g3(Dn/128, Mrows/128);     // 8 x 64
    gemm_tf32<1><<<g3, 256, 49152>>>(b_proj, out);
}

// round 10
// speedup vs baseline: 2.4425x; 1.7950x over previous
#include <cuda_runtime.h>
#include <cuda_fp16.h>
#include <math.h>
#include <stdint.h>

// Problem constants
#define Bn 4
#define Tn 2048
#define Dn 1024
#define Hn 16
#define HS 64
#define Mrows (Bn*Tn)          // 8192

// Scratch (device globals; no runtime allocation allowed)
__device__ __half g_q [(size_t)Bn*Hn*Tn*HS];   // [B,H,T,64] rope'd+scaled fp16
__device__ __half g_k [(size_t)Bn*Hn*Tn*HS];   // [B,H,T,64] rope'd fp16
__device__ __half g_vt[(size_t)Bn*Hn*HS*Tn];   // [B,H,64,T] V TRANSPOSED fp16
__device__ __half g_ao[(size_t)Mrows*Dn];      // attn out, packed fp16 A-tiles
__device__ float2 g_rope[Tn*32];               // (cos, sin) table
// fragment-major packed fp16 operands: [rowblk][ktile(32-k)][4096 halves]
__device__ __half g_xt[(size_t)Mrows*Dn];
__device__ __half g_wk[(size_t)3*Dn*Dn];
__device__ __half g_wp[(size_t)Dn*Dn];

// ---------------------------------------------------------------------------
// helpers
// ---------------------------------------------------------------------------
__device__ __forceinline__ float ex2(float x) {
    float y;
    asm("ex2.approx.f32 %0, %1;" : "=f"(y) : "f"(x));
    return y;
}

// fp16 mma: D(f32) += A(f16 m16k16) * B(f16 k16n8)
__device__ __forceinline__ void mma_f16(float c[4],
                                        uint32_t a0, uint32_t a1, uint32_t a2, uint32_t a3,
                                        uint32_t b0, uint32_t b1)
{
    asm volatile(
        "mma.sync.aligned.m16n8k16.row.col.f32.f16.f16.f32 "
        "{%0,%1,%2,%3}, {%4,%5,%6,%7}, {%8,%9}, {%0,%1,%2,%3};\n"
        : "+f"(c[0]), "+f"(c[1]), "+f"(c[2]), "+f"(c[3])
        : "r"(a0), "r"(a1), "r"(a2), "r"(a3), "r"(b0), "r"(b1));
}

__device__ __forceinline__ void cpa16(uint32_t dst_smem, const void* src) {
    asm volatile("cp.async.cg.shared.global [%0], [%1], 16;" :: "r"(dst_smem), "l"(src));
}
#define CP_COMMIT()  asm volatile("cp.async.commit_group;")
#define CP_WAIT(n)   asm volatile("cp.async.wait_group " #n ";")

// word (32-bit = 2 halves) offset within a 128x32 fp16 tile (2048 words)
// p = k-pair index 0..15 (k = 2p)
__device__ __forceinline__ int offA_h(int m, int p) {
    return (((((m >> 4) * 2 + (p >> 3)) * 8 + (m & 7)) * 4 + (p & 3)) * 4)
           + ((p >> 2) & 1) * 2 + ((m >> 3) & 1);
}
__device__ __forceinline__ int offB_h(int n, int p) {
    return (((((n >> 3) * 2 + (p >> 3)) * 8 + (n & 7)) * 4 + (p & 3)) * 2)
           + ((p >> 2) & 1);
}

// ---------------------------------------------------------------------------
// RoPE table init
// ---------------------------------------------------------------------------
__global__ void rope_init()
{
    int idx = blockIdx.x * blockDim.x + threadIdx.x;  // 0..65535
    int t = idx >> 5;
    int i = idx & 31;
    float theta = powf(10000.0f, (float)i * (-2.0f / 64.0f));
    float ang = (float)t * theta;
    float sn, cs;
    sincosf(ang, &sn, &cs);
    g_rope[idx] = make_float2(cs, sn);
}

// ---------------------------------------------------------------------------
// Pack src[M,1024] (row-major fp32) into fragment-major fp16 128x32 tiles.
// sel: 0 -> g_xt (A-pack), 1 -> g_wk (B-pack), 2 -> g_wp (B-pack)
// grid = (32 ktiles, M/128)
// ---------------------------------------------------------------------------
__global__ void __launch_bounds__(256) pack_op(int sel, const float* __restrict__ src)
{
    __shared__ __align__(16) __half sm[4096];
    const int k0 = blockIdx.x * 32;
    const int m0 = blockIdx.y * 128;
    const int tid = threadIdx.x;
    __half* dst = (sel == 0) ? g_xt : (sel == 1) ? g_wk : g_wp;
    const bool isA = (sel == 0);

    #pragma unroll
    for (int l = 0; l < 4; l++) {
        int idx = tid + l * 256;          // 1024 float4 slots (128 rows x 8)
        int row = idx >> 3;
        int c4 = (idx & 7) * 4;
        float4 v = *(const float4*)(src + (size_t)(m0 + row) * 1024 + k0 + c4);
        int p = c4 >> 1;                  // even pair index
        __half2 w0 = __floats2half2_rn(v.x, v.y);
        __half2 w1 = __floats2half2_rn(v.z, v.w);
        int o0 = isA ? offA_h(row, p)     : offB_h(row, p);
        int o1 = isA ? offA_h(row, p + 1) : offB_h(row, p + 1);
        *(__half2*)&sm[o0 * 2] = w0;
        *(__half2*)&sm[o1 * 2] = w1;
    }
    __syncthreads();
    size_t gb = ((size_t)blockIdx.y * 32 + blockIdx.x) * 4096;  // halves
    #pragma unroll
    for (int l = 0; l < 2; l++) {
        int i = tid + l * 256;            // 512 uint4
        *(uint4*)&dst[gb + (size_t)i * 8] = *(uint4*)&sm[i * 8];
    }
}

// ---------------------------------------------------------------------------
// fp16 tensor-core GEMM on PACKED operands: C[M,N] = A @ W^T, K=1024.
// Block 128x128, BK=32, 256 threads = 8 warps (2x4), warp tile 64x32.
// 3-stage cp.async pipeline, one barrier per 32-k tile.
// MODE 0: A=g_xt, W=g_wk, QKV epilogue (RoPE, fp16 q/k, transposed fp16 v)
// MODE 1: A=g_ao (packed by attention), W=g_wp, proj epilogue (bias -> out)
// ---------------------------------------------------------------------------
template<int MODE>
__global__ void __launch_bounds__(256) gemm_f16(const float* __restrict__ bias,
                                                float* __restrict__ out)
{
    extern __shared__ __align__(16) uint32_t gsm[];
    uint32_t* As = gsm;            // [3][2048 words]
    uint32_t* Ws = gsm + 3 * 2048;

    const int m0 = blockIdx.y * 128;
    const int n0 = blockIdx.x * 128;
    const int tid = threadIdx.x;
    const int wid = tid >> 5;
    const int lane = tid & 31;
    const int wm = wid >> 2;
    const int wn = wid & 3;
    const int gq = lane >> 2;
    const int tq = lane & 3;

    const __half* Abase = (MODE == 1) ? g_ao : g_xt;
    const __half* Wbase = (MODE == 1) ? g_wp : g_wk;
    const __half* Atiles = Abase + (size_t)blockIdx.y * 32 * 4096;
    const __half* Wtiles = Wbase + (size_t)blockIdx.x * 32 * 4096;

    const uint32_t sA = (uint32_t)__cvta_generic_to_shared(As);
    const uint32_t sW = (uint32_t)__cvta_generic_to_shared(Ws);

    float acc[4][4][4];
    #pragma unroll
    for (int mt = 0; mt < 4; mt++)
        #pragma unroll
        for (int nt = 0; nt < 4; nt++)
            #pragma unroll
            for (int r = 0; r < 4; r++) acc[mt][nt][r] = 0.f;

    // prologue: tiles 0,1 (2048 words each operand; 8 words/thread = 2 cpa16)
    #pragma unroll
    for (int p = 0; p < 2; p++) {
        cpa16(sA + (p * 2048 + tid * 8 + 0) * 4, Atiles + (size_t)p * 4096 + tid * 16 + 0);
        cpa16(sA + (p * 2048 + tid * 8 + 4) * 4, Atiles + (size_t)p * 4096 + tid * 16 + 8);
        cpa16(sW + (p * 2048 + tid * 8 + 0) * 4, Wtiles + (size_t)p * 4096 + tid * 16 + 0);
        cpa16(sW + (p * 2048 + tid * 8 + 4) * 4, Wtiles + (size_t)p * 4096 + tid * 16 + 8);
        CP_COMMIT();
    }

    int st = 0;
    for (int kt = 0; kt < 32; kt++) {
        if (kt < 31) { CP_WAIT(1); } else { CP_WAIT(0); }
        __syncthreads();

        if (kt + 2 < 32) {
            int stn = st + 2; if (stn >= 3) stn -= 3;
            const __half* At = Atiles + (size_t)(kt + 2) * 4096;
            const __half* Wt = Wtiles + (size_t)(kt + 2) * 4096;
            cpa16(sA + (stn * 2048 + tid * 8 + 0) * 4, At + tid * 16 + 0);
            cpa16(sA + (stn * 2048 + tid * 8 + 4) * 4, At + tid * 16 + 8);
            cpa16(sW + (stn * 2048 + tid * 8 + 0) * 4, Wt + tid * 16 + 0);
            cpa16(sW + (stn * 2048 + tid * 8 + 4) * 4, Wt + tid * 16 + 8);
            CP_COMMIT();
        }

        const uint32_t* Acur = As + st * 2048;
        const uint32_t* Wcur = Ws + st * 2048;
        #pragma unroll
        for (int ks = 0; ks < 2; ks++) {
            uint4 af[4];
            uint2 bf[4];
            #pragma unroll
            for (int mt = 0; mt < 4; mt++)
                af[mt] = *(const uint4*)&Acur[((((wm * 4 + mt) * 2 + ks) * 8 + gq) * 4 + tq) * 4];
            #pragma unroll
            for (int nt = 0; nt < 4; nt++)
                bf[nt] = *(const uint2*)&Wcur[((((wn * 4 + nt) * 2 + ks) * 8 + gq) * 4 + tq) * 2];
            #pragma unroll
            for (int mt = 0; mt < 4; mt++)
                #pragma unroll
                for (int nt = 0; nt < 4; nt++)
                    mma_f16(acc[mt][nt], af[mt].x, af[mt].y, af[mt].z, af[mt].w,
                            bf[nt].x, bf[nt].y);
        }
        st = (st == 2) ? 0 : st + 1;
    }

    if (MODE == 0) {
        const float QSC = 0.125f * 1.4426950408889634f;  // scale * log2(e)
        #pragma unroll
        for (int mt = 0; mt < 4; mt++) {
            #pragma unroll
            for (int r = 0; r < 2; r++) {
                int m = m0 + wm * 64 + mt * 16 + gq + r * 8;
                int bb = m >> 11;
                int tt = m & 2047;
                #pragma unroll
                for (int nt = 0; nt < 4; nt++) {
                    int col = n0 + wn * 32 + nt * 8 + 2 * tq;
                    int which = col >> 10;
                    int rem = col & 1023;
                    int h = rem >> 6;
                    int d = rem & 63;
                    int bh = bb * Hn + h;
                    float e = acc[mt][nt][r * 2 + 0];
                    float o = acc[mt][nt][r * 2 + 1];
                    if (which == 2) {
                        // V transposed: [bh][d][t]
                        size_t vo = ((size_t)bh * HS + d) * Tn + tt;
                        g_vt[vo]      = __float2half_rn(e);
                        g_vt[vo + Tn] = __float2half_rn(o);
                    } else {
                        float2 cs = g_rope[tt * 32 + (d >> 1)];
                        float t1 = e * cs.x - o * cs.y;
                        float t2 = e * cs.y + o * cs.x;
                        size_t off = ((size_t)bh * Tn + tt) * HS + d;
                        if (which == 0) {
                            *(__half2*)(g_k + off) = __floats2half2_rn(t1, t2);
                        } else {
                            *(__half2*)(g_q + off) = __floats2half2_rn(t1 * QSC, t2 * QSC);
                        }
                    }
                }
            }
        }
    } else {
        #pragma unroll
        for (int mt = 0; mt < 4; mt++) {
            #pragma unroll
            for (int r = 0; r < 2; r++) {
                int m = m0 + wm * 64 + mt * 16 + gq + r * 8;
                #pragma unroll
                for (int nt = 0; nt < 4; nt++) {
                    int col = n0 + wn * 32 + nt * 8 + 2 * tq;
                    float2 v2;
                    v2.x = acc[mt][nt][r * 2 + 0] + bias[col + 0];
                    v2.y = acc[mt][nt][r * 2 + 1] + bias[col + 1];
                    *(float2*)(out + (size_t)m * 1024 + col) = v2;
                }
            }
        }
    }
}

// ---------------------------------------------------------------------------
// fp16 tensor-core causal flash attention (mma m16n8k16), m32 warp tiles.
// Block: 128 q-rows, 4 warps x m32, 2 CTAs/SM. 2-stage cp.async K/Vt pipeline.
// Q/K row-major fp16; V pre-transposed (g_vt) so PV B-frags are contiguous.
// Epilogue packs fp16 A-tiles into g_ao for the proj GEMM.
// grid = (16, 64); heavy q-blocks first. smem pitch 36 words (72 halves).
// ---------------------------------------------------------------------------
#define AT_PITCH 36                       // words per 64-half row
#define KS_ST (64*AT_PITCH)               // 2304 words per stage
#define SMEM_ATTN ((2*KS_ST*2 + 128*AT_PITCH) * 4)   // K,Vt double-buffer + Ps

__global__ void __launch_bounds__(128, 2) attn_mma()
{
    extern __shared__ __align__(16) uint32_t smw[];
    uint32_t* KsB = smw;                  // [2][64][36]
    uint32_t* VsB = KsB + 2 * KS_ST;      // [2][64][36]
    uint32_t* Ps  = VsB + 2 * KS_ST;      // [128][36]  Q staging / P / O packing

    const int bh = blockIdx.y;
    const int qt = gridDim.x - 1 - blockIdx.x;
    const int tid = threadIdx.x;
    const int wid = tid >> 5;
    const int lane = tid & 31;
    const int gq = lane >> 2;
    const int tq = lane & 3;
    const int qb = qt * 128;
    const int wrow = wid * 32;

    const __half* Qp = g_q + (size_t)bh * Tn * HS;
    const __half* Kp = g_k + (size_t)bh * Tn * HS;
    const __half* Vtp = g_vt + (size_t)bh * HS * Tn;

    const uint32_t sK = (uint32_t)__cvta_generic_to_shared(KsB);
    const uint32_t sV = (uint32_t)__cvta_generic_to_shared(VsB);

    // K/Vt staging: 64 rows x 8 chunks(16B); 512 chunks / 128 thr = 4 each
    // prologue: tile 0 -> stage 0
    #pragma unroll
    for (int l = 0; l < 4; l++) {
        int c = tid + l * 128;
        int rr = c >> 3;
        int ci = c & 7;
        cpa16(sK + (rr * AT_PITCH + ci * 4) * 4, Kp + (size_t)rr * HS + ci * 8);
        cpa16(sV + (rr * AT_PITCH + ci * 4) * 4, Vtp + (size_t)rr * Tn + ci * 8);
    }
    CP_COMMIT();

    // stage Q (128 rows x 8 chunks = 1024 chunks / 128 thr = 8 each)
    #pragma unroll
    for (int l = 0; l < 8; l++) {
        int c = tid + l * 128;
        int rr = c >> 3;
        int ci = c & 7;
        uint4 v = *(const uint4*)(Qp + (size_t)(qb + rr) * HS + ci * 8);
        *(uint4*)&Ps[rr * AT_PITCH + ci * 4] = v;
    }
    __syncthreads();

    int roff[2][2];
    #pragma unroll
    for (int s = 0; s < 2; s++) {
        roff[s][0] = (wrow + 16 * s + gq) * AT_PITCH;
        roff[s][1] = (wrow + 16 * s + gq + 8) * AT_PITCH;
    }

    // Q fragments: [s][kk(4 k16-steps)][4 regs]
    uint32_t qf[2][4][4];
    #pragma unroll
    for (int s = 0; s < 2; s++)
        #pragma unroll
        for (int kk = 0; kk < 4; kk++) {
            qf[s][kk][0] = Ps[roff[s][0] + kk * 8 + tq];
            qf[s][kk][1] = Ps[roff[s][1] + kk * 8 + tq];
            qf[s][kk][2] = Ps[roff[s][0] + kk * 8 + tq + 4];
            qf[s][kk][3] = Ps[roff[s][1] + kk * 8 + tq + 4];
        }

    float O[2][8][4];
    #pragma unroll
    for (int s = 0; s < 2; s++)
        #pragma unroll
        for (int nt = 0; nt < 8; nt++)
            #pragma unroll
            for (int r = 0; r < 4; r++) O[s][nt][r] = 0.f;
    float mrow[2][2], lrow_[2][2];
    #pragma unroll
    for (int s = 0; s < 2; s++) {
        mrow[s][0] = -INFINITY; mrow[s][1] = -INFINITY;
        lrow_[s][0] = 0.f;      lrow_[s][1] = 0.f;
    }

    const int ntiles = 2 * qt + 2;
    int st = 0;
    for (int kt = 0; kt < ntiles; kt++) {
        const int k0 = kt * 64;
        CP_WAIT(0);
        __syncthreads();

        if (kt + 1 < ntiles) {
            int stn = st ^ 1;
            #pragma unroll
            for (int l = 0; l < 4; l++) {
                int c = tid + l * 128;
                int rr = c >> 3;
                int ci = c & 7;
                cpa16(sK + (stn * KS_ST + rr * AT_PITCH + ci * 4) * 4,
                      Kp + (size_t)(k0 + 64 + rr) * HS + ci * 8);
                cpa16(sV + (stn * KS_ST + rr * AT_PITCH + ci * 4) * 4,
                      Vtp + (size_t)rr * Tn + k0 + 64 + ci * 8);
            }
            CP_COMMIT();
        }

        if (k0 <= qb + wrow + 31) {
            const uint32_t* Ks = KsB + st * KS_ST;
            const uint32_t* Vs = VsB + st * KS_ST;

            // ---- S = Q K^T ---- (B frag: K[key][d] pairs)
            float S[2][8][4];
            #pragma unroll
            for (int s = 0; s < 2; s++)
                #pragma unroll
                for (int nt = 0; nt < 8; nt++)
                    #pragma unroll
                    for (int r = 0; r < 4; r++) S[s][nt][r] = 0.f;

            #pragma unroll
            for (int kk = 0; kk < 4; kk++) {
                #pragma unroll
                for (int nt = 0; nt < 8; nt++) {
                    uint32_t b0 = Ks[(nt * 8 + gq) * AT_PITCH + kk * 8 + tq];
                    uint32_t b1 = Ks[(nt * 8 + gq) * AT_PITCH + kk * 8 + tq + 4];
                    mma_f16(S[0][nt], qf[0][kk][0], qf[0][kk][1], qf[0][kk][2], qf[0][kk][3], b0, b1);
                    mma_f16(S[1][nt], qf[1][kk][0], qf[1][kk][1], qf[1][kk][2], qf[1][kk][3], b0, b1);
                }
            }

            // ---- causal mask ----
            if (k0 + 63 > qb + wrow) {
                #pragma unroll
                for (int s = 0; s < 2; s++) {
                    int row0 = qb + wrow + 16 * s + gq;
                    #pragma unroll
                    for (int nt = 0; nt < 8; nt++) {
                        int col = k0 + nt * 8 + 2 * tq;
                        if (col     > row0)     S[s][nt][0] = -INFINITY;
                        if (col + 1 > row0)     S[s][nt][1] = -INFINITY;
                        if (col     > row0 + 8) S[s][nt][2] = -INFINITY;
                        if (col + 1 > row0 + 8) S[s][nt][3] = -INFINITY;
                    }
                }
            }

            // ---- online softmax + fp16 P store ----
            __syncwarp();
            #pragma unroll
            for (int s = 0; s < 2; s++) {
                float cm0 = -INFINITY, cm1 = -INFINITY;
                #pragma unroll
                for (int nt = 0; nt < 8; nt++) {
                    cm0 = fmaxf(cm0, fmaxf(S[s][nt][0], S[s][nt][1]));
                    cm1 = fmaxf(cm1, fmaxf(S[s][nt][2], S[s][nt][3]));
                }
                cm0 = fmaxf(cm0, __shfl_xor_sync(0xffffffff, cm0, 1));
                cm0 = fmaxf(cm0, __shfl_xor_sync(0xffffffff, cm0, 2));
                cm1 = fmaxf(cm1, __shfl_xor_sync(0xffffffff, cm1, 1));
                cm1 = fmaxf(cm1, __shfl_xor_sync(0xffffffff, cm1, 2));

                float mn0 = fmaxf(mrow[s][0], cm0);
                float mn1 = fmaxf(mrow[s][1], cm1);
                float c0 = ex2(mrow[s][0] - mn0);
                float c1 = ex2(mrow[s][1] - mn1);
                lrow_[s][0] *= c0; lrow_[s][1] *= c1;
                #pragma unroll
                for (int nt = 0; nt < 8; nt++) {
                    O[s][nt][0] *= c0; O[s][nt][1] *= c0;
                    O[s][nt][2] *= c1; O[s][nt][3] *= c1;
                }
                mrow[s][0] = mn0; mrow[s][1] = mn1;

                #pragma unroll
                for (int nt = 0; nt < 8; nt++) {
                    float p0 = ex2(S[s][nt][0] - mn0);
                    float p1 = ex2(S[s][nt][1] - mn0);
                    float p2 = ex2(S[s][nt][2] - mn1);
                    float p3 = ex2(S[s][nt][3] - mn1);
                    lrow_[s][0] += p0 + p1;
                    lrow_[s][1] += p2 + p3;
                    // key pair index = nt*4 + tq
                    __half2 w0 = __floats2half2_rn(p0, p1);
                    __half2 w1 = __floats2half2_rn(p2, p3);
                    Ps[roff[s][0] + nt * 4 + tq] = *(uint32_t*)&w0;
                    Ps[roff[s][1] + nt * 4 + tq] = *(uint32_t*)&w1;
                }
            }
            __syncwarp();

            // ---- O += P V ---- (A=P frags from Ps; B=Vt[d][key] pairs)
            #pragma unroll
            for (int kk = 0; kk < 4; kk++) {
                uint32_t a[2][4];
                #pragma unroll
                for (int s = 0; s < 2; s++) {
                    a[s][0] = Ps[roff[s][0] + kk * 8 + tq];
                    a[s][1] = Ps[roff[s][1] + kk * 8 + tq];
                    a[s][2] = Ps[roff[s][0] + kk * 8 + tq + 4];
                    a[s][3] = Ps[roff[s][1] + kk * 8 + tq + 4];
                }
                #pragma unroll
                for (int nt = 0; nt < 8; nt++) {
                    uint32_t b0 = Vs[(nt * 8 + gq) * AT_PITCH + kk * 8 + tq];
                    uint32_t b1 = Vs[(nt * 8 + gq) * AT_PITCH + kk * 8 + tq + 4];
                    mma_f16(O[0][nt], a[0][0], a[0][1], a[0][2], a[0][3], b0, b1);
                    mma_f16(O[1][nt], a[1][0], a[1][1], a[1][2], a[1][3], b0, b1);
                }
            }
        }
        st ^= 1;
    }

    // ---- finalize: pack normalized O into fp16 A-tiles in g_ao ----
    const int bb = bh >> 4;
    const int h = bh & 15;
    __syncthreads();   // all warps done with Ps / mainloop
    #pragma unroll
    for (int s = 0; s < 2; s++) {
        float l0 = lrow_[s][0], l1 = lrow_[s][1];
        l0 += __shfl_xor_sync(0xffffffff, l0, 1);
        l0 += __shfl_xor_sync(0xffffffff, l0, 2);
        l1 += __shfl_xor_sync(0xffffffff, l1, 1);
        l1 += __shfl_xor_sync(0xffffffff, l1, 2);
        float inv0 = 1.f / l0;
        float inv1 = 1.f / l1;
        int m0l = wrow + 16 * s + gq;
        int m1l = m0l + 8;
        #pragma unroll
        for (int nt = 0; nt < 8; nt++) {
            int pg = nt * 4 + tq;          // col pair 0..31 within head
            int ktl = pg >> 4;             // local k-tile (d 0..31 / 32..63)
            int pin = pg & 15;
            __half2 w0 = __floats2half2_rn(O[s][nt][0] * inv0, O[s][nt][1] * inv0);
            __half2 w1 = __floats2half2_rn(O[s][nt][2] * inv1, O[s][nt][3] * inv1);
            Ps[ktl * 2048 + offA_h(m0l, pin)] = *(uint32_t*)&w0;
            Ps[ktl * 2048 + offA_h(m1l, pin)] = *(uint32_t*)&w1;
        }
    }
    __syncthreads();
    // store 2 tiles = 4096 words = 8192 halves = 1024 uint4; 8 per thread
    // word w of Ps -> halves 2w,2w+1 of dst  (FIX: was copying half the data
    // with a word/half unit mismatch)
    {
        __half* dst = g_ao + (((size_t)(bb * 16 + qt) * 32) + h * 2) * 4096;
        #pragma unroll
        for (int l = 0; l < 8; l++) {
            int i = tid + l * 128;        // 0..1023
            *(uint4*)&dst[(size_t)i * 8] = *(uint4*)&Ps[i * 4];
        }
    }
}

// ---------------------------------------------------------------------------
extern "C" void kernel_launch(void* const* d_in, const int* in_sizes, int n_in,
                              void* d_out, int out_size)
{
    const float* x      = (const float*)d_in[0];
    const float* w_kqv  = (const float*)d_in[1];
    const float* w_proj = (const float*)d_in[2];
    const float* b_proj = (const float*)d_in[3];
    float* out = (float*)d_out;

    cudaFuncSetAttribute(attn_mma, cudaFuncAttributeMaxDynamicSharedMemorySize, SMEM_ATTN);
    cudaFuncSetAttribute(gemm_f16<0>, cudaFuncAttributeMaxDynamicSharedMemorySize, 49152);
    cudaFuncSetAttribute(gemm_f16<1>, cudaFuncAttributeMaxDynamicSharedMemorySize, 49152);

    rope_init<<<64, 1024>>>();
    {
        dim3 gx(32, Mrows/128);      // 32 x 64
        pack_op<<<gx, 256>>>(0, x);
        dim3 gk(32, 3*Dn/128);       // 32 x 24
        pack_op<<<gk, 256>>>(1, w_kqv);
        dim3 gp(32, Dn/128);         // 32 x 8
        pack_op<<<gp, 256>>>(2, w_proj);
    }

    dim3 g1(3*Dn/128, Mrows/128);   // 24 x 64
    gemm_f16<0><<<g1, 256, 49152>>>(nullptr, nullptr);

    dim3 g2(Tn/128, Bn*Hn);         // 16 x 64
    attn_mma<<<g2, 128, SMEM_ATTN>>>();

    dim3 g3(Dn/128, Mrows/128);     // 8 x 64
    gemm_f16<1><<<g3, 256, 49152>>>(b_proj, out);
}